// round 13
// baseline (speedup 1.0000x reference)
#include <cuda_runtime.h>
#include <math_constants.h>

#define BB 16
#define SS 128
#define MM 128
#define NP 127
#define EPSF 1e-5f

// ---------------- device scratch (static, no allocation) ----------------
__device__ __align__(16) float g_nodes[BB][SS][MM];   // leaf node vectors
__device__ __align__(16) float g_y[BB][NP][MM];       // cached y per pair (init)
__device__ float g_loss[BB][SS];                      // cached loss per pair (init)
__device__ float g_accv[BB];
// fused weights, block-transposed: W12B[q][o][d] = W12[4q+d][o]
__device__ __align__(16) float g_W12B[64][128][4];
__device__ float g_b12[128];
__device__ __align__(16) float g_W34B[32][256][4];
__device__ float g_b34[256];

// ---------------- f32x2 packed FMA helpers ----------------
__device__ __forceinline__ void fma2(unsigned long long& acc, unsigned long long w, unsigned long long x) {
    asm("fma.rn.f32x2 %0, %1, %2, %0;" : "+l"(acc) : "l"(w), "l"(x));
}
__device__ __forceinline__ float sum2(unsigned long long a) {
    return __uint_as_float((unsigned)(a & 0xffffffffULL)) + __uint_as_float((unsigned)(a >> 32));
}
// order-preserving float -> uint key
__device__ __forceinline__ unsigned fkey(float f) {
    unsigned u = __float_as_uint(f);
    return (u & 0x80000000u) ? ~u : (u | 0x80000000u);
}

// ---------------- fused weight kernel: W12 = W1@W2, W34 = W3@W4 ----------------
__global__ void kfuse(const float* __restrict__ W1, const float* __restrict__ b1,
                      const float* __restrict__ W2, const float* __restrict__ b2,
                      const float* __restrict__ W3, const float* __restrict__ b3,
                      const float* __restrict__ W4, const float* __restrict__ b4) {
    __shared__ float row[192];
    int bid = blockIdx.x;
    if (bid < 257) {
        int k = bid;                      // 0..255 = W1 row, 256 = bias
        const float* src = (k < 256) ? (W1 + (size_t)k * 192) : b1;
        for (int m = threadIdx.x; m < 192; m += 256) row[m] = src[m];
        __syncthreads();
        if (threadIdx.x < 128) {
            int o = threadIdx.x;
            float acc = 0.f;
#pragma unroll 8
            for (int m = 0; m < 192; m++) acc += row[m] * W2[m * 128 + o];
            if (k < 256) g_W12B[k >> 2][o][k & 3] = acc;
            else         g_b12[o] = acc + b2[o];
        }
    } else {
        int k = bid - 257;                // 0..127 = W3 row, 128 = bias
        const float* src = (k < 128) ? (W3 + (size_t)k * 192) : b3;
        for (int m = threadIdx.x; m < 192; m += 256) row[m] = src[m];
        __syncthreads();
        int o = threadIdx.x;              // 0..255
        float acc = 0.f;
#pragma unroll 8
        for (int m = 0; m < 192; m++) acc += row[m] * W4[m * 256 + o];
        if (k < 128) g_W34B[k >> 2][o][k & 3] = acc;
        else         g_b34[o] = acc + b4[o];
    }
}

// ---------------- embedding gather (inline dtype detect) ----------------
__global__ void k_embed(const void* __restrict__ inp, const float* __restrict__ emb) {
    __shared__ int s64;
    int t = threadIdx.x;
    if (t == 0) s64 = 1;
    __syncthreads();
    for (int i2 = t * 2 + 1; i2 < BB * SS; i2 += 2 * blockDim.x)
        if (((const int*)inp)[i2] != 0) s64 = 0;
    __syncthreads();
    int i = blockIdx.x * blockDim.x + t;
    if (i >= BB * SS * MM) return;
    int m = i & (MM - 1);
    int bs = i >> 7;
    long long tok;
    if (s64) tok = ((const long long*)inp)[bs];
    else     tok = (long long)((const int*)inp)[bs];
    if (tok < 0) tok = 0;
    if (tok > 2999) tok = 2999;
    ((float*)g_nodes)[i] = emb[(size_t)tok * MM + m];
}

// ---------------- warp reduce helpers ----------------
__device__ __forceinline__ float warp_sum(float v) {
#pragma unroll
    for (int off = 16; off; off >>= 1) v += __shfl_xor_sync(0xffffffffu, v, off);
    return v;
}
__device__ __forceinline__ float warp_max(float v) {
#pragma unroll
    for (int off = 16; off; off >>= 1) v = fmaxf(v, __shfl_xor_sync(0xffffffffu, v, off));
    return v;
}

// ---------------- initial pass: all 127 pairs, loss + y cache ----------------
__global__ void k_init_pairs() {
    int j  = blockIdx.x;
    int rg = blockIdx.y;
    __shared__ __align__(16) float sIn[4][256];
    __shared__ __align__(16) float sY[4][128];
    __shared__ __align__(16) float sXX[4][256];
    __shared__ float sLS[4][2];
    int t = threadIdx.x, lane = t & 31, wid = t >> 5;

    for (int i = t; i < 1024; i += 512) {
        int r = i >> 8, k = i & 255;
        int b = rg * 4 + r;
        sIn[r][k] = (k < 128) ? g_nodes[b][j + 1][k] : g_nodes[b][j][k - 128];
    }
    __syncthreads();

    {
        int r = t >> 7, o = t & 127;
        int b = rg * 4 + r;
        const float4* W = (const float4*)g_W12B;
        const float4* X = (const float4*)sIn[r];
        float acc = 0.f;
#pragma unroll 8
        for (int q = 0; q < 64; q++) {
            float4 w = W[q * 128 + o]; float4 x = X[q];
            acc += w.x * x.x + w.y * x.y + w.z * x.z + w.w * x.w;
        }
        acc += g_b12[o];
        sY[r][o] = acc;
        g_y[b][j][o] = acc;
    }
    __syncthreads();

    for (int ii = 0; ii < 2; ii++) {
        int oi = t + ii * 512;
        int r = oi >> 8, o = oi & 255;
        const float4* W = (const float4*)g_W34B;
        const float4* X = (const float4*)sY[r];
        float acc = 0.f;
#pragma unroll 8
        for (int q = 0; q < 32; q++) {
            float4 w = W[q * 256 + o]; float4 x = X[q];
            acc += w.x * x.x + w.y * x.y + w.z * x.z + w.w * x.w;
        }
        sXX[r][o] = acc + g_b34[o];
    }
    __syncthreads();

    if (wid < 8) {
        int r = wid >> 1, h = wid & 1;
        const float* x  = sXX[r] + h * 128;
        const float* nd = sIn[r] + h * 128;
        float mx = -CUDART_INF_F;
        for (int i2 = lane; i2 < 128; i2 += 32) mx = fmaxf(mx, x[i2]);
        mx = warp_max(mx);
        float se = 0.f, dt = 0.f, sn = 0.f;
        for (int i2 = lane; i2 < 128; i2 += 32) {
            float xv = x[i2], nv = nd[i2];
            se += expf(xv - mx); dt += nv * xv; sn += nv;
        }
        se = warp_sum(se); dt = warp_sum(dt); sn = warp_sum(sn);
        if (lane == 0) sLS[r][h] = sn * (mx + logf(se)) - dt;
    }
    __syncthreads();
    if (t < 4) {
        int b = rg * 4 + t;
        g_loss[b][j] = ((1.f + EPSF) * sLS[t][0] + (1.f + EPSF) * sLS[t][1]) / (2.f + EPSF);
    }
}

// ---------------- persistent scan: one CTA per batch ----------------
// dyn smem: sW34h (65536B, q rows {8..15,24..31}) + nodeSm (65536B) + ySm (65024B)
#define DYN_BYTES (65536 + 65536 + 65024)

__global__ void __launch_bounds__(512, 1)
k_scan(const float* __restrict__ Wk, const float* __restrict__ bk, float* __restrict__ out) {
    extern __shared__ __align__(16) float dyn[];
    float* sW34h  = dyn;               // 16384 floats: q in {8..15,24..31}
    float* nodeSm = dyn + 16384;       // 128*128 floats: leaf nodes
    float* ySm    = dyn + 32768;       // 127*128 floats, row = slot
    int b = blockIdx.x;
    int t = threadIdx.x, lane = t & 31, wid = t >> 5;

    // double-buffered scan state (parity-indexed)
    __shared__ int   permB[2][SS];     // <128: leaf row (nodeSm), >=128: ySm slot+128
    __shared__ float countsB[2][SS];
    __shared__ __align__(16) float lossB[2][SS];
    __shared__ int   ypermB[2][SS];
    __shared__ __align__(16) float sIn[2][256];     // linear (softmax)
    __shared__ __align__(16) float sInSw[2][256];   // k-swizzled: unit p=4i+h1
    __shared__ __align__(16) float sYSw[2][128];    // k-swizzled: unit p=2i+h2
    __shared__ __align__(16) float sXX[2][256];
    __shared__ float b12s[128], b34s[256];
    __shared__ float sLS[2][2];
    __shared__ float sAcc;
    __shared__ float sProvV;
    __shared__ int   sProvI;
    __shared__ float logits[8];

    const float INFV = CUDART_INF_F;

    // thread mappings
    int o1 = (t & 7) | ((t >> 2) & 0x78);     // layer1 output 0..127
    int h1 = (t >> 3) & 3;                    // layer1 k-split
    int o2 = (t & 15) | ((t >> 1) & 0xF0);    // layer2 output 0..255
    int h2 = (t >> 4) & 1;                    // layer2 k-split

    // one-time staging
    for (int i = t; i < 4096; i += 512) {     // W34 smem half
        int r = i >> 8;
        int q = (r < 8) ? (r + 8) : (r + 16);
        ((float4*)sW34h)[i] = ((const float4*)g_W34B)[q * 256 + (i & 255)];
    }
    for (int i = t; i < 4096; i += 512)       // leaves
        ((float4*)nodeSm)[i] = ((const float4*)g_nodes[b])[i];
    for (int i = t; i < 4064; i += 512)       // y cache
        ((float4*)ySm)[i] = ((const float4*)g_y[b])[i];
    if (t < 128) b12s[t] = g_b12[t];
    if (t < 256) b34s[t] = g_b34[t];
    if (t < SS) {
        permB[0][t] = t; countsB[0][t] = 1.f; ypermB[0][t] = t;
        lossB[0][t] = (t < NP) ? g_loss[b][t] : INFV;
    }
    if (t == 0) sAcc = 0.f;

    // W12 slice into registers (64 regs)
    ulonglong2 wr12[16];
#pragma unroll
    for (int i = 0; i < 16; i++)
        wr12[i] = ((const ulonglong2*)g_W12B)[(h1 * 16 + i) * 128 + o1];
    // W34 first-half slice into registers (32 regs)
    ulonglong2 wr34h[8];
#pragma unroll
    for (int i = 0; i < 8; i++)
        wr34h[i] = ((const ulonglong2*)g_W34B)[(h2 * 16 + i) * 256 + o2];
    __syncthreads();

    int L = SS;
    int par = 0;
    int pState = 0;   // prev step: pos | hasA<<8 | hasB<<9 (valid when step>0)
    for (int step = 0; step < SS - 1; step++) {
        int*   permC = permB[par];   float* cntC  = countsB[par];
        float* lossC = lossB[par];   int*   ypC   = ypermB[par];
        int np = par ^ 1;
        int*   permN = permB[np];    float* cntN  = countsB[np];
        float* lossN = lossB[np];    int*   ypN   = ypermB[np];

        // ---- P1: argmin ----
        int idx; float vw;
        if (step == 0) {
            // full REDUX path (every warp, no barrier)
            float4 lv4 = ((const float4*)lossC)[lane];
            int base = lane * 4;
            float v = (base < L - 1) ? lv4.x : INFV;
            int vi = base;
            if (base + 1 < L - 1 && lv4.y < v) { v = lv4.y; vi = base + 1; }
            if (base + 2 < L - 1 && lv4.z < v) { v = lv4.z; vi = base + 2; }
            if (base + 3 < L - 1 && lv4.w < v) { v = lv4.w; vi = base + 3; }
            unsigned key = fkey(v);
            unsigned kmin = __reduce_min_sync(0xffffffffu, key);
            unsigned msk = __ballot_sync(0xffffffffu, key == kmin);
            int srcl = __ffs(msk) - 1;
            idx = __shfl_sync(0xffffffffu, vi, srcl);
            vw = __shfl_sync(0xffffffffu, v, srcl);
        } else {
            // fast path: provisional + 2 candidate slots (bit-identical result)
            int pPos = pState & 0xff;
            float bv = sProvV; int bi = sProvI;
            if (pState & 0x100) {
                float v1 = lossC[pPos - 1];
                if (v1 < bv || (v1 == bv && (pPos - 1) < bi)) { bv = v1; bi = pPos - 1; }
            }
            if (pState & 0x200) {
                float v2 = lossC[pPos];
                if (v2 < bv || (v2 == bv && pPos < bi)) { bv = v2; bi = pPos; }
            }
            idx = bi; vw = bv;
        }
        if (t == 0) sAcc += vw;

        // ---- P2: scalar derivation + reads from OLD buffer ----
        int Ln = L - 1;
        int pos = (idx > 0) ? idx - 1 : 0;
        int lc  = (idx == 0) ? (L - 1) : (idx - 1);
        float fcnt = cntC[idx] + cntC[lc];
        int yF = ypC[idx];
        bool hasA = (idx > 0) && (pos >= 1);
        bool hasB = (pos <= Ln - 2);
        int rOld = (idx == 0) ? 1 : (pos + 2);
        int slotA = hasA ? ypC[pos - 1] : 0;
        int slotB = ypC[pos];
        float cA2 = hasA ? cntC[pos - 1] : 0.f;
        float cB1 = hasB ? cntC[rOld] : 0.f;
        int srcA = hasA ? permC[pos - 1] : 0;
        int srcB = hasB ? permC[rOld] : 0;
        const float* pA = (srcA < 128) ? (nodeSm + srcA * 128) : (ySm + (srcA - 128) * 128);
        const float* pB = (srcB < 128) ? (nodeSm + srcB * 128) : (ySm + (srcB - 128) * 128);

        // unified copy source (stale tails land in never-read slots)
        int pv = 0, yv = 0; float cv = 0.f, lv = 0.f;
        float4 gv = make_float4(0.f, 0.f, 0.f, 0.f);
        if (t < 128) {
            int srcI = (idx > 0 && t > pos && t < 127) ? t + 1 : t;
            pv = permC[srcI]; cv = cntC[srcI];
            lv = lossC[srcI]; yv = ypC[srcI];
            int p = t >> 6, q4 = t & 63;
            if (p == 0) {
                if (q4 < 32) gv = ((const float4*)(ySm + yF * 128))[q4];
                else if (hasA) gv = ((const float4*)pA)[q4 - 32];
            } else {
                if (q4 >= 32) gv = ((const float4*)(ySm + yF * 128))[q4 - 32];
                else if (hasB) gv = ((const float4*)pB)[q4];
            }
        }

        // ---- P3: writes to NEW buffer + sIn (disjoint from OLD: no barrier) ----
        if (t < 128) {
            permN[t] = (t == pos) ? (128 + yF) : pv;
            cntN[t]  = (t == pos) ? fcnt : cv;
            lossN[t] = lv; ypN[t] = yv;
            int p = t >> 6, q4 = t & 63;
            ((float4*)sIn[p])[q4] = gv;
            int sw = ((q4 & 15) << 2) | (q4 >> 4);
            ((float4*)sInSw[p])[sw] = gv;
        }
        __syncthreads();   // B1

        // ---- P4: layer1 (W12 regs, conflict-free swizzled x) ----
        {
            const ulonglong2* XA = (const ulonglong2*)sInSw[0];
            const ulonglong2* XB = (const ulonglong2*)sInSw[1];
            unsigned long long a0 = 0, a1 = 0, c0 = 0, c1 = 0;
#pragma unroll
            for (int i = 0; i < 16; i++) {
                ulonglong2 w = wr12[i];
                ulonglong2 xa = XA[i * 4 + h1], xb = XB[i * 4 + h1];
                fma2(a0, w.x, xa.x); fma2(a1, w.y, xa.y);
                fma2(c0, w.x, xb.x); fma2(c1, w.y, xb.y);
            }
            float yA = sum2(a0) + sum2(a1);
            float yB = sum2(c0) + sum2(c1);
            yA += __shfl_xor_sync(0xffffffffu, yA, 8);
            yA += __shfl_xor_sync(0xffffffffu, yA, 16);
            yB += __shfl_xor_sync(0xffffffffu, yB, 8);
            yB += __shfl_xor_sync(0xffffffffu, yB, 16);
            if (h1 == 0) {
                yA += b12s[o1]; yB += b12s[o1];
                int q = o1 >> 2;
                int idxSw = ((((q & 15) << 1) | (q >> 4)) << 2) | (o1 & 3);
                sYSw[0][idxSw] = yA; sYSw[1][idxSw] = yB;
                if (hasA) ySm[slotA * 128 + o1] = yA;
                if (hasB) ySm[slotB * 128 + o1] = yB;
            }
        }
        __syncthreads();   // B2

        // ---- P5: layer2 (W34 half regs + half smem) ----
        {
            const ulonglong2* Wv = (const ulonglong2*)sW34h;
            const ulonglong2* YA = (const ulonglong2*)sYSw[0];
            const ulonglong2* YB = (const ulonglong2*)sYSw[1];
            unsigned long long a0 = 0, a1 = 0, c0 = 0, c1 = 0;
#pragma unroll
            for (int i = 0; i < 8; i++) {
                ulonglong2 w = wr34h[i];
                ulonglong2 ya = YA[i * 2 + h2], yb = YB[i * 2 + h2];
                fma2(a0, w.x, ya.x); fma2(a1, w.y, ya.y);
                fma2(c0, w.x, yb.x); fma2(c1, w.y, yb.y);
            }
#pragma unroll
            for (int i = 8; i < 16; i++) {
                ulonglong2 w = Wv[((i - 8) + h2 * 8) * 256 + o2];
                ulonglong2 ya = YA[i * 2 + h2], yb = YB[i * 2 + h2];
                fma2(a0, w.x, ya.x); fma2(a1, w.y, ya.y);
                fma2(c0, w.x, yb.x); fma2(c1, w.y, yb.y);
            }
            float xA = sum2(a0) + sum2(a1);
            float xB = sum2(c0) + sum2(c1);
            xA += __shfl_xor_sync(0xffffffffu, xA, 16);
            xB += __shfl_xor_sync(0xffffffffu, xB, 16);
            if (h2 == 0) {
                sXX[0][o2] = xA + b34s[o2];
                sXX[1][o2] = xB + b34s[o2];
            }
        }
        __syncthreads();   // B3

        // ---- P6: softmax (warps 0-3) ∥ provisional argmin (warp 8) ----
        if (wid < 4) {
            int p = wid >> 1, h = wid & 1;
            const float* x  = sXX[p] + h * 128;
            const float* nd = sIn[p] + h * 128;
            float mx = -INFV;
#pragma unroll
            for (int i2 = 0; i2 < 4; i2++) mx = fmaxf(mx, x[lane + i2 * 32]);
            mx = warp_max(mx);
            float se = 0.f, dt = 0.f, sn = 0.f;
#pragma unroll
            for (int i2 = 0; i2 < 4; i2++) {
                float xv = x[lane + i2 * 32], nv = nd[lane + i2 * 32];
                se += expf(xv - mx); dt += nv * xv; sn += nv;
            }
            se = warp_sum(se); dt = warp_sum(dt); sn = warp_sum(sn);
            if (lane == 0) sLS[p][h] = sn * (mx + logf(se)) - dt;
            asm volatile("bar.sync 1, 128;" ::: "memory");
            if (t == 0) {
                if (hasA)
                    lossN[pos - 1] = ((fcnt + EPSF) * sLS[0][0] + (cA2 + EPSF) * sLS[0][1]) / (fcnt + cA2 + EPSF);
                if (hasB)
                    lossN[pos] = ((cB1 + EPSF) * sLS[1][0] + (fcnt + EPSF) * sLS[1][1]) / (cB1 + fcnt + EPSF);
            }
        } else if (wid == 8) {
            // provisional argmin over lossN excluding {pos-1, pos}, j < Ln-1
            float4 lv4 = ((const float4*)lossN)[lane];
            int j0 = lane * 4;
            float v = INFV; int vi = 0;
            {
                float vals[4] = {lv4.x, lv4.y, lv4.z, lv4.w};
#pragma unroll
                for (int d = 0; d < 4; d++) {
                    int j = j0 + d;
                    bool ok = (j < Ln - 1) && (j != pos - 1) && (j != pos);
                    if (ok && vals[d] < v) { v = vals[d]; vi = j; }
                }
            }
            unsigned key = fkey(v);
            unsigned kmin = __reduce_min_sync(0xffffffffu, key);
            unsigned msk = __ballot_sync(0xffffffffu, key == kmin);
            int srcl = __ffs(msk) - 1;
            int viw = __shfl_sync(0xffffffffu, vi, srcl);
            float vmin = __shfl_sync(0xffffffffu, v, srcl);
            if (lane == 0) { sProvV = vmin; sProvI = viw; }
        }
        __syncthreads();   // B4 (loss writes + prov visible)

        pState = pos | (hasA ? 0x100 : 0) | (hasB ? 0x200 : 0);
        L = Ln;
        par = np;
    }

    // ---- final classifier on root node ----
    if (t < 5) {
        int src = permB[par][0];
        const float* root = (src < 128) ? (nodeSm + src * 128) : (ySm + (src - 128) * 128);
        float a = bk[t];
#pragma unroll 8
        for (int k2 = 0; k2 < 128; k2++) a += root[k2] * Wk[k2 * 5 + t];
        logits[t] = a;
    }
    __syncthreads();
    if (t == 0) {
        int best = 0; float bv = logits[0];
#pragma unroll
        for (int o = 1; o < 5; o++) if (logits[o] > bv) { bv = logits[o]; best = o; }
        out[b] = (float)best;
        g_accv[b] = sAcc;
    }
}

// ---------------- finalize: mean acc ----------------
__global__ void k_final(float* out) {
    int t = threadIdx.x;
    float v = (t < BB) ? g_accv[t] : 0.f;
#pragma unroll
    for (int off = 16; off; off >>= 1) v += __shfl_down_sync(0xffffffffu, v, off);
    if (t == 0) out[BB] = v / (float)BB;
}

// ---------------- launcher ----------------
extern "C" void kernel_launch(void* const* d_in, const int* in_sizes, int n_in,
                              void* d_out, int out_size) {
    const void*  inp = d_in[0];
    const float* emb = (const float*)d_in[1];
    const float* W1 = (const float*)d_in[2];
    const float* b1 = (const float*)d_in[3];
    const float* W2 = (const float*)d_in[4];
    const float* b2 = (const float*)d_in[5];
    const float* W3 = (const float*)d_in[6];
    const float* b3 = (const float*)d_in[7];
    const float* W4 = (const float*)d_in[8];
    const float* b4 = (const float*)d_in[9];
    const float* Wk = (const float*)d_in[10];
    const float* bk = (const float*)d_in[11];
    float* out = (float*)d_out;

    static bool attr_set = false;
    if (!attr_set) {
        cudaFuncSetAttribute(k_scan, cudaFuncAttributeMaxDynamicSharedMemorySize, DYN_BYTES);
        attr_set = true;
    }

    kfuse<<<386, 256>>>(W1, b1, W2, b2, W3, b3, W4, b4);
    k_embed<<<(BB * SS * MM + 511) / 512, 512>>>(inp, emb);
    k_init_pairs<<<dim3(NP, 4), 512>>>();
    k_scan<<<BB, 512, DYN_BYTES>>>(Wk, bk, out);
    k_final<<<1, 32>>>(out);
}

// round 14
// speedup vs baseline: 1.6276x; 1.6276x over previous
#include <cuda_runtime.h>
#include <math_constants.h>

#define BB 16
#define SS 128
#define MM 128
#define NP 127
#define EPSF 1e-5f

// ---------------- device scratch (static, no allocation) ----------------
__device__ __align__(16) float g_nodes[BB][SS][MM];   // leaf node vectors
__device__ __align__(16) float g_y[BB][NP][MM];       // cached y per pair (init)
__device__ float g_loss[BB][SS];                      // cached loss per pair (init)
__device__ float g_accv[BB];
// fused weights, block-transposed: W12B[q][o][d] = W12[4q+d][o]
__device__ __align__(16) float g_W12B[64][128][4];
__device__ float g_b12[128];
__device__ __align__(16) float g_W34B[32][256][4];
__device__ float g_b34[256];

// ---------------- f32x2 packed FMA helpers ----------------
__device__ __forceinline__ void fma2(unsigned long long& acc, unsigned long long w, unsigned long long x) {
    asm("fma.rn.f32x2 %0, %1, %2, %0;" : "+l"(acc) : "l"(w), "l"(x));
}
__device__ __forceinline__ float sum2(unsigned long long a) {
    return __uint_as_float((unsigned)(a & 0xffffffffULL)) + __uint_as_float((unsigned)(a >> 32));
}
// order-preserving float -> uint key
__device__ __forceinline__ unsigned fkey(float f) {
    unsigned u = __float_as_uint(f);
    return (u & 0x80000000u) ? ~u : (u | 0x80000000u);
}

// ---------------- fused weight kernel: W12 = W1@W2, W34 = W3@W4 ----------------
__global__ void kfuse(const float* __restrict__ W1, const float* __restrict__ b1,
                      const float* __restrict__ W2, const float* __restrict__ b2,
                      const float* __restrict__ W3, const float* __restrict__ b3,
                      const float* __restrict__ W4, const float* __restrict__ b4) {
    __shared__ float row[192];
    int bid = blockIdx.x;
    if (bid < 257) {
        int k = bid;                      // 0..255 = W1 row, 256 = bias
        const float* src = (k < 256) ? (W1 + (size_t)k * 192) : b1;
        for (int m = threadIdx.x; m < 192; m += 256) row[m] = src[m];
        __syncthreads();
        if (threadIdx.x < 128) {
            int o = threadIdx.x;
            float acc = 0.f;
#pragma unroll 8
            for (int m = 0; m < 192; m++) acc += row[m] * W2[m * 128 + o];
            if (k < 256) g_W12B[k >> 2][o][k & 3] = acc;
            else         g_b12[o] = acc + b2[o];
        }
    } else {
        int k = bid - 257;                // 0..127 = W3 row, 128 = bias
        const float* src = (k < 128) ? (W3 + (size_t)k * 192) : b3;
        for (int m = threadIdx.x; m < 192; m += 256) row[m] = src[m];
        __syncthreads();
        int o = threadIdx.x;              // 0..255
        float acc = 0.f;
#pragma unroll 8
        for (int m = 0; m < 192; m++) acc += row[m] * W4[m * 256 + o];
        if (k < 128) g_W34B[k >> 2][o][k & 3] = acc;
        else         g_b34[o] = acc + b4[o];
    }
}

// ---------------- embedding gather (inline dtype detect) ----------------
__global__ void k_embed(const void* __restrict__ inp, const float* __restrict__ emb) {
    __shared__ int s64;
    int t = threadIdx.x;
    if (t == 0) s64 = 1;
    __syncthreads();
    for (int i2 = t * 2 + 1; i2 < BB * SS; i2 += 2 * blockDim.x)
        if (((const int*)inp)[i2] != 0) s64 = 0;
    __syncthreads();
    int i = blockIdx.x * blockDim.x + t;
    if (i >= BB * SS * MM) return;
    int m = i & (MM - 1);
    int bs = i >> 7;
    long long tok;
    if (s64) tok = ((const long long*)inp)[bs];
    else     tok = (long long)((const int*)inp)[bs];
    if (tok < 0) tok = 0;
    if (tok > 2999) tok = 2999;
    ((float*)g_nodes)[i] = emb[(size_t)tok * MM + m];
}

// ---------------- warp reduce helpers ----------------
__device__ __forceinline__ float warp_sum(float v) {
#pragma unroll
    for (int off = 16; off; off >>= 1) v += __shfl_xor_sync(0xffffffffu, v, off);
    return v;
}
__device__ __forceinline__ float warp_max(float v) {
#pragma unroll
    for (int off = 16; off; off >>= 1) v = fmaxf(v, __shfl_xor_sync(0xffffffffu, v, off));
    return v;
}

// ---------------- initial pass: all 127 pairs, loss + y cache ----------------
__global__ void k_init_pairs() {
    int j  = blockIdx.x;
    int rg = blockIdx.y;
    __shared__ __align__(16) float sIn[4][256];
    __shared__ __align__(16) float sY[4][128];
    __shared__ __align__(16) float sXX[4][256];
    __shared__ float sLS[4][2];
    int t = threadIdx.x, lane = t & 31, wid = t >> 5;

    for (int i = t; i < 1024; i += 512) {
        int r = i >> 8, k = i & 255;
        int b = rg * 4 + r;
        sIn[r][k] = (k < 128) ? g_nodes[b][j + 1][k] : g_nodes[b][j][k - 128];
    }
    __syncthreads();

    {
        int r = t >> 7, o = t & 127;
        int b = rg * 4 + r;
        const float4* W = (const float4*)g_W12B;
        const float4* X = (const float4*)sIn[r];
        float acc = 0.f;
#pragma unroll 8
        for (int q = 0; q < 64; q++) {
            float4 w = W[q * 128 + o]; float4 x = X[q];
            acc += w.x * x.x + w.y * x.y + w.z * x.z + w.w * x.w;
        }
        acc += g_b12[o];
        sY[r][o] = acc;
        g_y[b][j][o] = acc;
    }
    __syncthreads();

    for (int ii = 0; ii < 2; ii++) {
        int oi = t + ii * 512;
        int r = oi >> 8, o = oi & 255;
        const float4* W = (const float4*)g_W34B;
        const float4* X = (const float4*)sY[r];
        float acc = 0.f;
#pragma unroll 8
        for (int q = 0; q < 32; q++) {
            float4 w = W[q * 256 + o]; float4 x = X[q];
            acc += w.x * x.x + w.y * x.y + w.z * x.z + w.w * x.w;
        }
        sXX[r][o] = acc + g_b34[o];
    }
    __syncthreads();

    if (wid < 8) {
        int r = wid >> 1, h = wid & 1;
        const float* x  = sXX[r] + h * 128;
        const float* nd = sIn[r] + h * 128;
        float mx = -CUDART_INF_F;
        for (int i2 = lane; i2 < 128; i2 += 32) mx = fmaxf(mx, x[i2]);
        mx = warp_max(mx);
        float se = 0.f, dt = 0.f, sn = 0.f;
        for (int i2 = lane; i2 < 128; i2 += 32) {
            float xv = x[i2], nv = nd[i2];
            se += expf(xv - mx); dt += nv * xv; sn += nv;
        }
        se = warp_sum(se); dt = warp_sum(dt); sn = warp_sum(sn);
        if (lane == 0) sLS[r][h] = sn * (mx + logf(se)) - dt;
    }
    __syncthreads();
    if (t < 4) {
        int b = rg * 4 + t;
        g_loss[b][j] = ((1.f + EPSF) * sLS[t][0] + (1.f + EPSF) * sLS[t][1]) / (2.f + EPSF);
    }
}

// ---------------- persistent scan: one CTA per batch ----------------
// dyn smem: sW34h (65536B, q rows {8..15,24..31}) + nodeSm (65536B) + ySm (65024B)
#define DYN_BYTES (65536 + 65536 + 65024)

__global__ void __launch_bounds__(512, 1)
k_scan(const float* __restrict__ Wk, const float* __restrict__ bk, float* __restrict__ out) {
    extern __shared__ __align__(16) float dyn[];
    float* sW34h  = dyn;               // 16384 floats: q in {8..15,24..31}
    float* nodeSm = dyn + 16384;       // 128*128 floats: leaf nodes
    float* ySm    = dyn + 32768;       // 127*128 floats, row = slot
    int b = blockIdx.x;
    int t = threadIdx.x, lane = t & 31, wid = t >> 5;

    // double-buffered scan state (parity-indexed)
    __shared__ int   permB[2][SS];     // <128: leaf row (nodeSm), >=128: ySm slot+128
    __shared__ float countsB[2][SS];
    __shared__ __align__(16) float lossB[2][SS];
    __shared__ int   ypermB[2][SS];
    __shared__ __align__(16) float sIn[2][256];     // linear (softmax)
    __shared__ __align__(16) float sInSw[2][256];   // k-swizzled: unit p=4i+h1
    __shared__ __align__(16) float sYSw[2][128];    // k-swizzled: unit p=2i+h2
    __shared__ __align__(16) float sXX[2][256];
    __shared__ float b12s[128], b34s[256];
    __shared__ float sLS[2][2];
    __shared__ float sAcc;
    __shared__ float sProvV;
    __shared__ int   sProvI;
    __shared__ float logits[8];

    const float INFV = CUDART_INF_F;

    // thread mappings
    int o1 = (t & 7) | ((t >> 2) & 0x78);     // layer1 output 0..127
    int h1 = (t >> 3) & 3;                    // layer1 k-split
    int o2 = (t & 15) | ((t >> 1) & 0xF0);    // layer2 output 0..255
    int h2 = (t >> 4) & 1;                    // layer2 k-split

    // one-time staging
    for (int i = t; i < 4096; i += 512) {     // W34 smem half
        int r = i >> 8;
        int q = (r < 8) ? (r + 8) : (r + 16);
        ((float4*)sW34h)[i] = ((const float4*)g_W34B)[q * 256 + (i & 255)];
    }
    for (int i = t; i < 4096; i += 512)       // leaves
        ((float4*)nodeSm)[i] = ((const float4*)g_nodes[b])[i];
    for (int i = t; i < 4064; i += 512)       // y cache
        ((float4*)ySm)[i] = ((const float4*)g_y[b])[i];
    if (t < 128) b12s[t] = g_b12[t];
    if (t < 256) b34s[t] = g_b34[t];
    if (t < SS) {
        permB[0][t] = t; countsB[0][t] = 1.f; ypermB[0][t] = t;
        lossB[0][t] = (t < NP) ? g_loss[b][t] : INFV;
    }
    if (t == 0) sAcc = 0.f;

    // W12 slice into registers (64 regs)
    ulonglong2 wr12[16];
#pragma unroll
    for (int i = 0; i < 16; i++)
        wr12[i] = ((const ulonglong2*)g_W12B)[(h1 * 16 + i) * 128 + o1];
    // W34 first-half slice into registers (32 regs)
    ulonglong2 wr34h[8];
#pragma unroll
    for (int i = 0; i < 8; i++)
        wr34h[i] = ((const ulonglong2*)g_W34B)[(h2 * 16 + i) * 256 + o2];
    __syncthreads();

    int L = SS;
    int par = 0;
    int pState = 0;   // prev step: pos | hasA<<8 | hasB<<9 (valid when step>0)
    for (int step = 0; step < SS - 1; step++) {
        int*   permC = permB[par];   float* cntC  = countsB[par];
        float* lossC = lossB[par];   int*   ypC   = ypermB[par];
        int np = par ^ 1;
        int*   permN = permB[np];    float* cntN  = countsB[np];
        float* lossN = lossB[np];    int*   ypN   = ypermB[np];

        // ---- P1: argmin ----
        int idx; float vw;
        if (step == 0) {
            // full REDUX path (every warp, no barrier)
            float4 lv4 = ((const float4*)lossC)[lane];
            int base = lane * 4;
            float v = (base < L - 1) ? lv4.x : INFV;
            int vi = base;
            if (base + 1 < L - 1 && lv4.y < v) { v = lv4.y; vi = base + 1; }
            if (base + 2 < L - 1 && lv4.z < v) { v = lv4.z; vi = base + 2; }
            if (base + 3 < L - 1 && lv4.w < v) { v = lv4.w; vi = base + 3; }
            unsigned key = fkey(v);
            unsigned kmin = __reduce_min_sync(0xffffffffu, key);
            unsigned msk = __ballot_sync(0xffffffffu, key == kmin);
            int srcl = __ffs(msk) - 1;
            idx = __shfl_sync(0xffffffffu, vi, srcl);
            vw = __shfl_sync(0xffffffffu, v, srcl);
        } else {
            // fast path: provisional + 2 candidate slots (bit-identical result)
            int pPos = pState & 0xff;
            float bv = sProvV; int bi = sProvI;
            if (pState & 0x100) {
                float v1 = lossC[pPos - 1];
                if (v1 < bv || (v1 == bv && (pPos - 1) < bi)) { bv = v1; bi = pPos - 1; }
            }
            if (pState & 0x200) {
                float v2 = lossC[pPos];
                if (v2 < bv || (v2 == bv && pPos < bi)) { bv = v2; bi = pPos; }
            }
            idx = bi; vw = bv;
        }
        if (t == 0) sAcc += vw;

        // ---- P2: scalar derivation + reads from OLD buffer ----
        int Ln = L - 1;
        int pos = (idx > 0) ? idx - 1 : 0;
        int lc  = (idx == 0) ? (L - 1) : (idx - 1);
        float fcnt = cntC[idx] + cntC[lc];
        int yF = ypC[idx];
        bool hasA = (idx > 0) && (pos >= 1);
        bool hasB = (pos <= Ln - 2);
        int rOld = (idx == 0) ? 1 : (pos + 2);
        int slotA = hasA ? ypC[pos - 1] : 0;
        int slotB = ypC[pos];
        float cA2 = hasA ? cntC[pos - 1] : 0.f;
        float cB1 = hasB ? cntC[rOld] : 0.f;
        int srcA = hasA ? permC[pos - 1] : 0;
        int srcB = hasB ? permC[rOld] : 0;
        const float* pA = (srcA < 128) ? (nodeSm + srcA * 128) : (ySm + (srcA - 128) * 128);
        const float* pB = (srcB < 128) ? (nodeSm + srcB * 128) : (ySm + (srcB - 128) * 128);

        // unified copy source (stale tails land in never-read slots)
        int pv = 0, yv = 0; float cv = 0.f, lv = 0.f;
        float4 gv = make_float4(0.f, 0.f, 0.f, 0.f);
        if (t < 128) {
            int srcI = (idx > 0 && t > pos && t < 127) ? t + 1 : t;
            pv = permC[srcI]; cv = cntC[srcI];
            lv = lossC[srcI]; yv = ypC[srcI];
            int p = t >> 6, q4 = t & 63;
            if (p == 0) {
                if (q4 < 32) gv = ((const float4*)(ySm + yF * 128))[q4];
                else if (hasA) gv = ((const float4*)pA)[q4 - 32];
            } else {
                if (q4 >= 32) gv = ((const float4*)(ySm + yF * 128))[q4 - 32];
                else if (hasB) gv = ((const float4*)pB)[q4];
            }
        }

        // ---- P3: writes to NEW buffer + sIn (disjoint from OLD: no barrier) ----
        if (t < 128) {
            permN[t] = (t == pos) ? (128 + yF) : pv;
            cntN[t]  = (t == pos) ? fcnt : cv;
            lossN[t] = lv; ypN[t] = yv;
            int p = t >> 6, q4 = t & 63;
            ((float4*)sIn[p])[q4] = gv;
            int sw = ((q4 & 15) << 2) | (q4 >> 4);
            ((float4*)sInSw[p])[sw] = gv;
        }
        __syncthreads();   // B1

        // ---- P4: layer1 (W12 regs, conflict-free swizzled x) ----
        {
            const ulonglong2* XA = (const ulonglong2*)sInSw[0];
            const ulonglong2* XB = (const ulonglong2*)sInSw[1];
            unsigned long long a0 = 0, a1 = 0, c0 = 0, c1 = 0;
#pragma unroll
            for (int i = 0; i < 16; i++) {
                ulonglong2 w = wr12[i];
                ulonglong2 xa = XA[i * 4 + h1], xb = XB[i * 4 + h1];
                fma2(a0, w.x, xa.x); fma2(a1, w.y, xa.y);
                fma2(c0, w.x, xb.x); fma2(c1, w.y, xb.y);
            }
            float yA = sum2(a0) + sum2(a1);
            float yB = sum2(c0) + sum2(c1);
            yA += __shfl_xor_sync(0xffffffffu, yA, 8);
            yA += __shfl_xor_sync(0xffffffffu, yA, 16);
            yB += __shfl_xor_sync(0xffffffffu, yB, 8);
            yB += __shfl_xor_sync(0xffffffffu, yB, 16);
            if (h1 == 0) {
                yA += b12s[o1]; yB += b12s[o1];
                int q = o1 >> 2;
                int idxSw = ((((q & 15) << 1) | (q >> 4)) << 2) | (o1 & 3);
                sYSw[0][idxSw] = yA; sYSw[1][idxSw] = yB;
                if (hasA) ySm[slotA * 128 + o1] = yA;
                if (hasB) ySm[slotB * 128 + o1] = yB;
            }
        }
        __syncthreads();   // B2

        // ---- P5: layer2 (W34 half regs + half smem) ----
        {
            const ulonglong2* Wv = (const ulonglong2*)sW34h;
            const ulonglong2* YA = (const ulonglong2*)sYSw[0];
            const ulonglong2* YB = (const ulonglong2*)sYSw[1];
            unsigned long long a0 = 0, a1 = 0, c0 = 0, c1 = 0;
#pragma unroll
            for (int i = 0; i < 8; i++) {
                ulonglong2 w = wr34h[i];
                ulonglong2 ya = YA[i * 2 + h2], yb = YB[i * 2 + h2];
                fma2(a0, w.x, ya.x); fma2(a1, w.y, ya.y);
                fma2(c0, w.x, yb.x); fma2(c1, w.y, yb.y);
            }
#pragma unroll
            for (int i = 8; i < 16; i++) {
                ulonglong2 w = Wv[((i - 8) + h2 * 8) * 256 + o2];
                ulonglong2 ya = YA[i * 2 + h2], yb = YB[i * 2 + h2];
                fma2(a0, w.x, ya.x); fma2(a1, w.y, ya.y);
                fma2(c0, w.x, yb.x); fma2(c1, w.y, yb.y);
            }
            float xA = sum2(a0) + sum2(a1);
            float xB = sum2(c0) + sum2(c1);
            xA += __shfl_xor_sync(0xffffffffu, xA, 16);
            xB += __shfl_xor_sync(0xffffffffu, xB, 16);
            if (h2 == 0) {
                sXX[0][o2] = xA + b34s[o2];
                sXX[1][o2] = xB + b34s[o2];
            }
        }
        __syncthreads();   // B3

        // ---- P6: softmax (warps 0-3) ∥ provisional argmin (warp 8) ----
        if (wid < 4) {
            int p = wid >> 1, h = wid & 1;
            const float* x  = sXX[p] + h * 128;
            const float* nd = sIn[p] + h * 128;
            float mx = -INFV;
#pragma unroll
            for (int i2 = 0; i2 < 4; i2++) mx = fmaxf(mx, x[lane + i2 * 32]);
            mx = warp_max(mx);
            float se = 0.f, dt = 0.f, sn = 0.f;
#pragma unroll
            for (int i2 = 0; i2 < 4; i2++) {
                float xv = x[lane + i2 * 32], nv = nd[lane + i2 * 32];
                se += expf(xv - mx); dt += nv * xv; sn += nv;
            }
            se = warp_sum(se); dt = warp_sum(dt); sn = warp_sum(sn);
            if (lane == 0) sLS[p][h] = sn * (mx + logf(se)) - dt;
        } else if (wid == 8) {
            // provisional argmin over lossN excluding {pos-1, pos}, j < Ln-1
            float4 lv4 = ((const float4*)lossN)[lane];
            int j0 = lane * 4;
            float v = INFV; int vi = 0;
            {
                float vals[4] = {lv4.x, lv4.y, lv4.z, lv4.w};
#pragma unroll
                for (int d = 0; d < 4; d++) {
                    int j = j0 + d;
                    bool ok = (j < Ln - 1) && (j != pos - 1) && (j != pos);
                    if (ok && vals[d] < v) { v = vals[d]; vi = j; }
                }
            }
            unsigned key = fkey(v);
            unsigned kmin = __reduce_min_sync(0xffffffffu, key);
            unsigned msk = __ballot_sync(0xffffffffu, key == kmin);
            int srcl = __ffs(msk) - 1;
            int viw = __shfl_sync(0xffffffffu, vi, srcl);
            float vmin = __shfl_sync(0xffffffffu, v, srcl);
            if (lane == 0) { sProvV = vmin; sProvI = viw; }
        }
        __syncthreads();   // B4

        // ---- P7: loss updates into NEW buffer ----
        if (t == 0) {
            if (hasA)
                lossN[pos - 1] = ((fcnt + EPSF) * sLS[0][0] + (cA2 + EPSF) * sLS[0][1]) / (fcnt + cA2 + EPSF);
            if (hasB)
                lossN[pos] = ((cB1 + EPSF) * sLS[1][0] + (fcnt + EPSF) * sLS[1][1]) / (cB1 + fcnt + EPSF);
        }
        __syncthreads();   // B5 (loss writes + prov visible)

        pState = pos | (hasA ? 0x100 : 0) | (hasB ? 0x200 : 0);
        L = Ln;
        par = np;
    }

    // ---- final classifier on root node ----
    if (t < 5) {
        int src = permB[par][0];
        const float* root = (src < 128) ? (nodeSm + src * 128) : (ySm + (src - 128) * 128);
        float a = bk[t];
#pragma unroll 8
        for (int k2 = 0; k2 < 128; k2++) a += root[k2] * Wk[k2 * 5 + t];
        logits[t] = a;
    }
    __syncthreads();
    if (t == 0) {
        int best = 0; float bv = logits[0];
#pragma unroll
        for (int o = 1; o < 5; o++) if (logits[o] > bv) { bv = logits[o]; best = o; }
        out[b] = (float)best;
        g_accv[b] = sAcc;
    }
}

// ---------------- finalize: mean acc ----------------
__global__ void k_final(float* out) {
    int t = threadIdx.x;
    float v = (t < BB) ? g_accv[t] : 0.f;
#pragma unroll
    for (int off = 16; off; off >>= 1) v += __shfl_down_sync(0xffffffffu, v, off);
    if (t == 0) out[BB] = v / (float)BB;
}

// ---------------- launcher ----------------
extern "C" void kernel_launch(void* const* d_in, const int* in_sizes, int n_in,
                              void* d_out, int out_size) {
    const void*  inp = d_in[0];
    const float* emb = (const float*)d_in[1];
    const float* W1 = (const float*)d_in[2];
    const float* b1 = (const float*)d_in[3];
    const float* W2 = (const float*)d_in[4];
    const float* b2 = (const float*)d_in[5];
    const float* W3 = (const float*)d_in[6];
    const float* b3 = (const float*)d_in[7];
    const float* W4 = (const float*)d_in[8];
    const float* b4 = (const float*)d_in[9];
    const float* Wk = (const float*)d_in[10];
    const float* bk = (const float*)d_in[11];
    float* out = (float*)d_out;

    static bool attr_set = false;
    if (!attr_set) {
        cudaFuncSetAttribute(k_scan, cudaFuncAttributeMaxDynamicSharedMemorySize, DYN_BYTES);
        attr_set = true;
    }

    kfuse<<<386, 256>>>(W1, b1, W2, b2, W3, b3, W4, b4);
    k_embed<<<(BB * SS * MM + 511) / 512, 512>>>(inp, emb);
    k_init_pairs<<<dim3(NP, 4), 512>>>();
    k_scan<<<BB, 512, DYN_BYTES>>>(Wk, bk, out);
    k_final<<<1, 32>>>(out);
}

// round 15
// speedup vs baseline: 1.6701x; 1.0261x over previous
#include <cuda_runtime.h>
#include <math_constants.h>

#define BB 16
#define SS 128
#define MM 128
#define NP 127
#define EPSF 1e-5f

// ---------------- device scratch (static, no allocation) ----------------
__device__ __align__(16) float g_nodes[BB][SS][MM];   // leaf node vectors
__device__ __align__(16) float g_y[BB][NP][MM];       // cached y per pair (init)
__device__ float g_loss[BB][SS];                      // cached loss per pair (init)
__device__ float g_accv[BB];
// fused weights, block-transposed: W12B[q][o][d] = W12[4q+d][o]
__device__ __align__(16) float g_W12B[64][128][4];
__device__ float g_b12[128];
__device__ __align__(16) float g_W34B[32][256][4];
__device__ float g_b34[256];

// ---------------- f32x2 packed FMA helpers ----------------
__device__ __forceinline__ void fma2(unsigned long long& acc, unsigned long long w, unsigned long long x) {
    asm("fma.rn.f32x2 %0, %1, %2, %0;" : "+l"(acc) : "l"(w), "l"(x));
}
__device__ __forceinline__ float sum2(unsigned long long a) {
    return __uint_as_float((unsigned)(a & 0xffffffffULL)) + __uint_as_float((unsigned)(a >> 32));
}
// order-preserving float -> uint key
__device__ __forceinline__ unsigned fkey(float f) {
    unsigned u = __float_as_uint(f);
    return (u & 0x80000000u) ? ~u : (u | 0x80000000u);
}

// ---------------- fused weight kernel: W12 = W1@W2, W34 = W3@W4 ----------------
__global__ void kfuse(const float* __restrict__ W1, const float* __restrict__ b1,
                      const float* __restrict__ W2, const float* __restrict__ b2,
                      const float* __restrict__ W3, const float* __restrict__ b3,
                      const float* __restrict__ W4, const float* __restrict__ b4) {
    __shared__ float row[192];
    int bid = blockIdx.x;
    if (bid < 257) {
        int k = bid;                      // 0..255 = W1 row, 256 = bias
        const float* src = (k < 256) ? (W1 + (size_t)k * 192) : b1;
        for (int m = threadIdx.x; m < 192; m += 256) row[m] = src[m];
        __syncthreads();
        if (threadIdx.x < 128) {
            int o = threadIdx.x;
            float acc = 0.f;
#pragma unroll 8
            for (int m = 0; m < 192; m++) acc += row[m] * W2[m * 128 + o];
            if (k < 256) g_W12B[k >> 2][o][k & 3] = acc;
            else         g_b12[o] = acc + b2[o];
        }
    } else {
        int k = bid - 257;                // 0..127 = W3 row, 128 = bias
        const float* src = (k < 128) ? (W3 + (size_t)k * 192) : b3;
        for (int m = threadIdx.x; m < 192; m += 256) row[m] = src[m];
        __syncthreads();
        int o = threadIdx.x;              // 0..255
        float acc = 0.f;
#pragma unroll 8
        for (int m = 0; m < 192; m++) acc += row[m] * W4[m * 256 + o];
        if (k < 128) g_W34B[k >> 2][o][k & 3] = acc;
        else         g_b34[o] = acc + b4[o];
    }
}

// ---------------- embedding gather (inline dtype detect) ----------------
__global__ void k_embed(const void* __restrict__ inp, const float* __restrict__ emb) {
    __shared__ int s64;
    int t = threadIdx.x;
    if (t == 0) s64 = 1;
    __syncthreads();
    for (int i2 = t * 2 + 1; i2 < BB * SS; i2 += 2 * blockDim.x)
        if (((const int*)inp)[i2] != 0) s64 = 0;
    __syncthreads();
    int i = blockIdx.x * blockDim.x + t;
    if (i >= BB * SS * MM) return;
    int m = i & (MM - 1);
    int bs = i >> 7;
    long long tok;
    if (s64) tok = ((const long long*)inp)[bs];
    else     tok = (long long)((const int*)inp)[bs];
    if (tok < 0) tok = 0;
    if (tok > 2999) tok = 2999;
    ((float*)g_nodes)[i] = emb[(size_t)tok * MM + m];
}

// ---------------- warp reduce helpers ----------------
__device__ __forceinline__ float warp_sum(float v) {
#pragma unroll
    for (int off = 16; off; off >>= 1) v += __shfl_xor_sync(0xffffffffu, v, off);
    return v;
}
__device__ __forceinline__ float warp_max(float v) {
#pragma unroll
    for (int off = 16; off; off >>= 1) v = fmaxf(v, __shfl_xor_sync(0xffffffffu, v, off));
    return v;
}

// ---------------- initial pass: all 127 pairs, loss + y cache ----------------
__global__ void k_init_pairs() {
    int j  = blockIdx.x;
    int rg = blockIdx.y;
    __shared__ __align__(16) float sIn[4][256];
    __shared__ __align__(16) float sY[4][128];
    __shared__ __align__(16) float sXX[4][256];
    __shared__ float sLS[4][2];
    int t = threadIdx.x, lane = t & 31, wid = t >> 5;

    for (int i = t; i < 1024; i += 512) {
        int r = i >> 8, k = i & 255;
        int b = rg * 4 + r;
        sIn[r][k] = (k < 128) ? g_nodes[b][j + 1][k] : g_nodes[b][j][k - 128];
    }
    __syncthreads();

    {
        int r = t >> 7, o = t & 127;
        int b = rg * 4 + r;
        const float4* W = (const float4*)g_W12B;
        const float4* X = (const float4*)sIn[r];
        float acc = 0.f;
#pragma unroll 8
        for (int q = 0; q < 64; q++) {
            float4 w = W[q * 128 + o]; float4 x = X[q];
            acc += w.x * x.x + w.y * x.y + w.z * x.z + w.w * x.w;
        }
        acc += g_b12[o];
        sY[r][o] = acc;
        g_y[b][j][o] = acc;
    }
    __syncthreads();

    for (int ii = 0; ii < 2; ii++) {
        int oi = t + ii * 512;
        int r = oi >> 8, o = oi & 255;
        const float4* W = (const float4*)g_W34B;
        const float4* X = (const float4*)sY[r];
        float acc = 0.f;
#pragma unroll 8
        for (int q = 0; q < 32; q++) {
            float4 w = W[q * 256 + o]; float4 x = X[q];
            acc += w.x * x.x + w.y * x.y + w.z * x.z + w.w * x.w;
        }
        sXX[r][o] = acc + g_b34[o];
    }
    __syncthreads();

    if (wid < 8) {
        int r = wid >> 1, h = wid & 1;
        const float* x  = sXX[r] + h * 128;
        const float* nd = sIn[r] + h * 128;
        float mx = -CUDART_INF_F;
        for (int i2 = lane; i2 < 128; i2 += 32) mx = fmaxf(mx, x[i2]);
        mx = warp_max(mx);
        float se = 0.f, dt = 0.f, sn = 0.f;
        for (int i2 = lane; i2 < 128; i2 += 32) {
            float xv = x[i2], nv = nd[i2];
            se += expf(xv - mx); dt += nv * xv; sn += nv;
        }
        se = warp_sum(se); dt = warp_sum(dt); sn = warp_sum(sn);
        if (lane == 0) sLS[r][h] = sn * (mx + logf(se)) - dt;
    }
    __syncthreads();
    if (t < 4) {
        int b = rg * 4 + t;
        g_loss[b][j] = ((1.f + EPSF) * sLS[t][0] + (1.f + EPSF) * sLS[t][1]) / (2.f + EPSF);
    }
}

// ---------------- persistent scan: one CTA per batch ----------------
// dyn smem: sW34h (65536B, q rows {8..15,24..31}) + nodeSm (65536B) + ySm (65024B)
#define DYN_BYTES (65536 + 65536 + 65024)

__global__ void __launch_bounds__(512, 1)
k_scan(const float* __restrict__ Wk, const float* __restrict__ bk, float* __restrict__ out) {
    extern __shared__ __align__(16) float dyn[];
    float* sW34h  = dyn;               // 16384 floats: q in {8..15,24..31}
    float* nodeSm = dyn + 16384;       // 128*128 floats: leaf nodes
    float* ySm    = dyn + 32768;       // 127*128 floats, row = slot
    int b = blockIdx.x;
    int t = threadIdx.x, lane = t & 31, wid = t >> 5;

    // double-buffered scan state (parity-indexed)
    __shared__ int   permB[2][SS];     // <128: leaf row (nodeSm), >=128: ySm slot+128
    __shared__ float countsB[2][SS];
    __shared__ __align__(16) float lossB[2][SS];
    __shared__ int   ypermB[2][SS];
    __shared__ __align__(16) float sIn[2][256];     // linear (softmax)
    __shared__ __align__(16) float sInSw[2][256];   // k-swizzled: unit p=4i+h1
    __shared__ __align__(16) float sYSw[2][128];    // k-swizzled: unit p=2i+h2
    __shared__ __align__(16) float sXX[2][256];
    __shared__ float b12s[128], b34s[256];
    __shared__ float sAcc;
    __shared__ float logits[8];

    const float INFV = CUDART_INF_F;

    // thread mappings
    int o1 = (t & 7) | ((t >> 2) & 0x78);     // layer1 output 0..127
    int h1 = (t >> 3) & 3;                    // layer1 k-split
    int o2 = (t & 15) | ((t >> 1) & 0xF0);    // layer2 output 0..255
    int h2 = (t >> 4) & 1;                    // layer2 k-split

    // one-time staging
    for (int i = t; i < 4096; i += 512) {     // W34 smem half
        int r = i >> 8;
        int q = (r < 8) ? (r + 8) : (r + 16);
        ((float4*)sW34h)[i] = ((const float4*)g_W34B)[q * 256 + (i & 255)];
    }
    for (int i = t; i < 4096; i += 512)       // leaves
        ((float4*)nodeSm)[i] = ((const float4*)g_nodes[b])[i];
    for (int i = t; i < 4064; i += 512)       // y cache
        ((float4*)ySm)[i] = ((const float4*)g_y[b])[i];
    if (t < 128) b12s[t] = g_b12[t];
    if (t < 256) b34s[t] = g_b34[t];
    if (t < SS) {
        permB[0][t] = t; countsB[0][t] = 1.f; ypermB[0][t] = t;
        lossB[0][t] = (t < NP) ? g_loss[b][t] : INFV;
    }
    if (t == 0) sAcc = 0.f;

    // W12 slice into registers (64 regs)
    ulonglong2 wr12[16];
#pragma unroll
    for (int i = 0; i < 16; i++)
        wr12[i] = ((const ulonglong2*)g_W12B)[(h1 * 16 + i) * 128 + o1];
    // W34 first-half slice into registers (32 regs)
    ulonglong2 wr34h[8];
#pragma unroll
    for (int i = 0; i < 8; i++)
        wr34h[i] = ((const ulonglong2*)g_W34B)[(h2 * 16 + i) * 256 + o2];
    __syncthreads();

    int L = SS;
    int par = 0;
    for (int step = 0; step < SS - 1; step++) {
        int*   permC = permB[par];   float* cntC  = countsB[par];
        float* lossC = lossB[par];   int*   ypC   = ypermB[par];
        int np = par ^ 1;
        int*   permN = permB[np];    float* cntN  = countsB[np];
        float* lossN = lossB[np];    int*   ypN   = ypermB[np];

        // ---- P1: argmin, redundant in EVERY warp (no barrier) ----
        float4 lv4 = ((const float4*)lossC)[lane];
        int base = lane * 4;
        float v = (base < L - 1) ? lv4.x : INFV;
        int vi = base;
        if (base + 1 < L - 1 && lv4.y < v) { v = lv4.y; vi = base + 1; }
        if (base + 2 < L - 1 && lv4.z < v) { v = lv4.z; vi = base + 2; }
        if (base + 3 < L - 1 && lv4.w < v) { v = lv4.w; vi = base + 3; }
        unsigned key = fkey(v);
        unsigned kmin = __reduce_min_sync(0xffffffffu, key);
        unsigned msk = __ballot_sync(0xffffffffu, key == kmin);
        int srcl = __ffs(msk) - 1;
        int idx = __shfl_sync(0xffffffffu, vi, srcl);
        float vw = __shfl_sync(0xffffffffu, v, srcl);
        if (t == 0) sAcc += vw;

        // ---- P2: scalar derivation + reads from OLD buffer ----
        int Ln = L - 1;
        int pos = (idx > 0) ? idx - 1 : 0;
        int lc  = (idx == 0) ? (L - 1) : (idx - 1);
        float fcnt = cntC[idx] + cntC[lc];
        int yF = ypC[idx];
        bool hasA = (idx > 0) && (pos >= 1);
        bool hasB = (pos <= Ln - 2);
        int rOld = (idx == 0) ? 1 : (pos + 2);
        int slotA = hasA ? ypC[pos - 1] : 0;
        int slotB = ypC[pos];
        float cA2 = hasA ? cntC[pos - 1] : 0.f;
        float cB1 = hasB ? cntC[rOld] : 0.f;
        int srcA = hasA ? permC[pos - 1] : 0;
        int srcB = hasB ? permC[rOld] : 0;
        const float* pA = (srcA < 128) ? (nodeSm + srcA * 128) : (ySm + (srcA - 128) * 128);
        const float* pB = (srcB < 128) ? (nodeSm + srcB * 128) : (ySm + (srcB - 128) * 128);

        // unified copy source (stale tails land in never-read slots)
        int pv = 0, yv = 0; float cv = 0.f, lv = 0.f;
        float4 gv = make_float4(0.f, 0.f, 0.f, 0.f);
        if (t < 128) {
            int srcI = (idx > 0 && t > pos && t < 127) ? t + 1 : t;
            pv = permC[srcI]; cv = cntC[srcI];
            lv = lossC[srcI]; yv = ypC[srcI];
            int p = t >> 6, q4 = t & 63;
            if (p == 0) {
                if (q4 < 32) gv = ((const float4*)(ySm + yF * 128))[q4];
                else if (hasA) gv = ((const float4*)pA)[q4 - 32];
            } else {
                if (q4 >= 32) gv = ((const float4*)(ySm + yF * 128))[q4 - 32];
                else if (hasB) gv = ((const float4*)pB)[q4];
            }
        }

        // ---- P3: writes to NEW buffer + sIn (disjoint from OLD: no barrier) ----
        if (t < 128) {
            permN[t] = (t == pos) ? (128 + yF) : pv;
            cntN[t]  = (t == pos) ? fcnt : cv;
            lossN[t] = lv; ypN[t] = yv;
            int p = t >> 6, q4 = t & 63;
            ((float4*)sIn[p])[q4] = gv;
            int sw = ((q4 & 15) << 2) | (q4 >> 4);
            ((float4*)sInSw[p])[sw] = gv;
        }
        __syncthreads();   // B1

        // ---- P4: layer1 (W12 regs, conflict-free swizzled x) ----
        {
            const ulonglong2* XA = (const ulonglong2*)sInSw[0];
            const ulonglong2* XB = (const ulonglong2*)sInSw[1];
            unsigned long long a0 = 0, a1 = 0, c0 = 0, c1 = 0;
#pragma unroll
            for (int i = 0; i < 16; i++) {
                ulonglong2 w = wr12[i];
                ulonglong2 xa = XA[i * 4 + h1], xb = XB[i * 4 + h1];
                fma2(a0, w.x, xa.x); fma2(a1, w.y, xa.y);
                fma2(c0, w.x, xb.x); fma2(c1, w.y, xb.y);
            }
            float yA = sum2(a0) + sum2(a1);
            float yB = sum2(c0) + sum2(c1);
            yA += __shfl_xor_sync(0xffffffffu, yA, 8);
            yA += __shfl_xor_sync(0xffffffffu, yA, 16);
            yB += __shfl_xor_sync(0xffffffffu, yB, 8);
            yB += __shfl_xor_sync(0xffffffffu, yB, 16);
            if (h1 == 0) {
                yA += b12s[o1]; yB += b12s[o1];
                int q = o1 >> 2;
                int idxSw = ((((q & 15) << 1) | (q >> 4)) << 2) | (o1 & 3);
                sYSw[0][idxSw] = yA; sYSw[1][idxSw] = yB;
                if (hasA) ySm[slotA * 128 + o1] = yA;
                if (hasB) ySm[slotB * 128 + o1] = yB;
            }
        }
        __syncthreads();   // B2

        // ---- P5: layer2 (W34 half regs + half smem) ----
        {
            const ulonglong2* Wv = (const ulonglong2*)sW34h;
            const ulonglong2* YA = (const ulonglong2*)sYSw[0];
            const ulonglong2* YB = (const ulonglong2*)sYSw[1];
            unsigned long long a0 = 0, a1 = 0, c0 = 0, c1 = 0;
#pragma unroll
            for (int i = 0; i < 8; i++) {
                ulonglong2 w = wr34h[i];
                ulonglong2 ya = YA[i * 2 + h2], yb = YB[i * 2 + h2];
                fma2(a0, w.x, ya.x); fma2(a1, w.y, ya.y);
                fma2(c0, w.x, yb.x); fma2(c1, w.y, yb.y);
            }
#pragma unroll
            for (int i = 8; i < 16; i++) {
                ulonglong2 w = Wv[((i - 8) + h2 * 8) * 256 + o2];
                ulonglong2 ya = YA[i * 2 + h2], yb = YB[i * 2 + h2];
                fma2(a0, w.x, ya.x); fma2(a1, w.y, ya.y);
                fma2(c0, w.x, yb.x); fma2(c1, w.y, yb.y);
            }
            float xA = sum2(a0) + sum2(a1);
            float xB = sum2(c0) + sum2(c1);
            xA += __shfl_xor_sync(0xffffffffu, xA, 16);
            xB += __shfl_xor_sync(0xffffffffu, xB, 16);
            if (h2 == 0) {
                sXX[0][o2] = xA + b34s[o2];
                sXX[1][o2] = xB + b34s[o2];
            }
        }
        __syncthreads();   // B3

        // ---- P6: softmax + loss write, ONE warp per pair (warps 0-1) ----
        if (wid < 2) {
            int p = wid;                 // pair
            int h = lane >> 4;           // half (0: ls1/right, 1: ls2/left)
            int l16 = lane & 15;
            const float* x  = sXX[p] + h * 128 + l16 * 8;
            const float* nd = sIn[p] + h * 128 + l16 * 8;
            float4 x0 = ((const float4*)x)[0], x1 = ((const float4*)x)[1];
            float4 n0 = ((const float4*)nd)[0], n1 = ((const float4*)nd)[1];
            // local max (tree)
            float mx = fmaxf(fmaxf(fmaxf(x0.x, x0.y), fmaxf(x0.z, x0.w)),
                             fmaxf(fmaxf(x1.x, x1.y), fmaxf(x1.z, x1.w)));
#pragma unroll
            for (int s = 1; s <= 8; s <<= 1) mx = fmaxf(mx, __shfl_xor_sync(0xffffffffu, mx, s));
            // local sums (trees)
            float se = (expf(x0.x - mx) + expf(x0.y - mx)) + (expf(x0.z - mx) + expf(x0.w - mx))
                     + (expf(x1.x - mx) + expf(x1.y - mx)) + (expf(x1.z - mx) + expf(x1.w - mx));
            float dt = (n0.x * x0.x + n0.y * x0.y) + (n0.z * x0.z + n0.w * x0.w)
                     + (n1.x * x1.x + n1.y * x1.y) + (n1.z * x1.z + n1.w * x1.w);
            float sn = (n0.x + n0.y) + (n0.z + n0.w) + (n1.x + n1.y) + (n1.z + n1.w);
#pragma unroll
            for (int s = 1; s <= 8; s <<= 1) {
                se += __shfl_xor_sync(0xffffffffu, se, s);
                dt += __shfl_xor_sync(0xffffffffu, dt, s);
                sn += __shfl_xor_sync(0xffffffffu, sn, s);
            }
            float ls = sn * (mx + logf(se)) - dt;
            float lsOther = __shfl_xor_sync(0xffffffffu, ls, 16);
            if (lane == 0) {
                float ls1 = ls, ls2 = lsOther;
                if (p == 0) {
                    if (hasA) lossN[pos - 1] = ((fcnt + EPSF) * ls1 + (cA2 + EPSF) * ls2) / (fcnt + cA2 + EPSF);
                } else {
                    if (hasB) lossN[pos] = ((cB1 + EPSF) * ls1 + (fcnt + EPSF) * ls2) / (cB1 + fcnt + EPSF);
                }
            }
        }
        __syncthreads();   // B4 (loss writes visible for next P1)

        L = Ln;
        par = np;
    }

    // ---- final classifier on root node ----
    if (t < 5) {
        int src = permB[par][0];
        const float* root = (src < 128) ? (nodeSm + src * 128) : (ySm + (src - 128) * 128);
        float a = bk[t];
#pragma unroll 8
        for (int k2 = 0; k2 < 128; k2++) a += root[k2] * Wk[k2 * 5 + t];
        logits[t] = a;
    }
    __syncthreads();
    if (t == 0) {
        int best = 0; float bv = logits[0];
#pragma unroll
        for (int o = 1; o < 5; o++) if (logits[o] > bv) { bv = logits[o]; best = o; }
        out[b] = (float)best;
        g_accv[b] = sAcc;
    }
}

// ---------------- finalize: mean acc ----------------
__global__ void k_final(float* out) {
    int t = threadIdx.x;
    float v = (t < BB) ? g_accv[t] : 0.f;
#pragma unroll
    for (int off = 16; off; off >>= 1) v += __shfl_down_sync(0xffffffffu, v, off);
    if (t == 0) out[BB] = v / (float)BB;
}

// ---------------- launcher ----------------
extern "C" void kernel_launch(void* const* d_in, const int* in_sizes, int n_in,
                              void* d_out, int out_size) {
    const void*  inp = d_in[0];
    const float* emb = (const float*)d_in[1];
    const float* W1 = (const float*)d_in[2];
    const float* b1 = (const float*)d_in[3];
    const float* W2 = (const float*)d_in[4];
    const float* b2 = (const float*)d_in[5];
    const float* W3 = (const float*)d_in[6];
    const float* b3 = (const float*)d_in[7];
    const float* W4 = (const float*)d_in[8];
    const float* b4 = (const float*)d_in[9];
    const float* Wk = (const float*)d_in[10];
    const float* bk = (const float*)d_in[11];
    float* out = (float*)d_out;

    static bool attr_set = false;
    if (!attr_set) {
        cudaFuncSetAttribute(k_scan, cudaFuncAttributeMaxDynamicSharedMemorySize, DYN_BYTES);
        attr_set = true;
    }

    kfuse<<<386, 256>>>(W1, b1, W2, b2, W3, b3, W4, b4);
    k_embed<<<(BB * SS * MM + 511) / 512, 512>>>(inp, emb);
    k_init_pairs<<<dim3(NP, 4), 512>>>();
    k_scan<<<BB, 512, DYN_BYTES>>>(Wk, bk, out);
    k_final<<<1, 32>>>(out);
}

// round 17
// speedup vs baseline: 1.6891x; 1.0114x over previous
#include <cuda_runtime.h>
#include <math_constants.h>

#define BB 16
#define SS 128
#define MM 128
#define NP 127
#define EPSF 1e-5f

// ---------------- device scratch (static, no allocation) ----------------
__device__ __align__(16) float g_nodes[BB][SS][MM];   // leaf node vectors
__device__ __align__(16) float g_y[BB][NP][MM];       // cached y per pair (init)
__device__ float g_loss[BB][SS];                      // cached loss per pair (init)
__device__ float g_accv[BB];
// fused weights, block-transposed: W12B[q][o][d] = W12[4q+d][o]
__device__ __align__(16) float g_W12B[64][128][4];
__device__ float g_b12[128];
__device__ __align__(16) float g_W34B[32][256][4];
__device__ float g_b34[256];

// ---------------- f32x2 packed FMA helpers ----------------
__device__ __forceinline__ void fma2(unsigned long long& acc, unsigned long long w, unsigned long long x) {
    asm("fma.rn.f32x2 %0, %1, %2, %0;" : "+l"(acc) : "l"(w), "l"(x));
}
__device__ __forceinline__ float sum2(unsigned long long a) {
    return __uint_as_float((unsigned)(a & 0xffffffffULL)) + __uint_as_float((unsigned)(a >> 32));
}
// order-preserving float -> uint key
__device__ __forceinline__ unsigned fkey(float f) {
    unsigned u = __float_as_uint(f);
    return (u & 0x80000000u) ? ~u : (u | 0x80000000u);
}

// ---------------- fused weight kernel: W12 = W1@W2, W34 = W3@W4 ----------------
__global__ void kfuse(const float* __restrict__ W1, const float* __restrict__ b1,
                      const float* __restrict__ W2, const float* __restrict__ b2,
                      const float* __restrict__ W3, const float* __restrict__ b3,
                      const float* __restrict__ W4, const float* __restrict__ b4) {
    __shared__ float row[192];
    int bid = blockIdx.x;
    if (bid < 257) {
        int k = bid;                      // 0..255 = W1 row, 256 = bias
        const float* src = (k < 256) ? (W1 + (size_t)k * 192) : b1;
        for (int m = threadIdx.x; m < 192; m += 256) row[m] = src[m];
        __syncthreads();
        if (threadIdx.x < 128) {
            int o = threadIdx.x;
            float acc = 0.f;
#pragma unroll 8
            for (int m = 0; m < 192; m++) acc += row[m] * W2[m * 128 + o];
            if (k < 256) g_W12B[k >> 2][o][k & 3] = acc;
            else         g_b12[o] = acc + b2[o];
        }
    } else {
        int k = bid - 257;                // 0..127 = W3 row, 128 = bias
        const float* src = (k < 128) ? (W3 + (size_t)k * 192) : b3;
        for (int m = threadIdx.x; m < 192; m += 256) row[m] = src[m];
        __syncthreads();
        int o = threadIdx.x;              // 0..255
        float acc = 0.f;
#pragma unroll 8
        for (int m = 0; m < 192; m++) acc += row[m] * W4[m * 256 + o];
        if (k < 128) g_W34B[k >> 2][o][k & 3] = acc;
        else         g_b34[o] = acc + b4[o];
    }
}

// ---------------- embedding gather (inline dtype detect) ----------------
__global__ void k_embed(const void* __restrict__ inp, const float* __restrict__ emb) {
    __shared__ int s64;
    int t = threadIdx.x;
    if (t == 0) s64 = 1;
    __syncthreads();
    for (int i2 = t * 2 + 1; i2 < BB * SS; i2 += 2 * blockDim.x)
        if (((const int*)inp)[i2] != 0) s64 = 0;
    __syncthreads();
    int i = blockIdx.x * blockDim.x + t;
    if (i >= BB * SS * MM) return;
    int m = i & (MM - 1);
    int bs = i >> 7;
    long long tok;
    if (s64) tok = ((const long long*)inp)[bs];
    else     tok = (long long)((const int*)inp)[bs];
    if (tok < 0) tok = 0;
    if (tok > 2999) tok = 2999;
    ((float*)g_nodes)[i] = emb[(size_t)tok * MM + m];
}

// ---------------- warp reduce helpers ----------------
__device__ __forceinline__ float warp_sum(float v) {
#pragma unroll
    for (int off = 16; off; off >>= 1) v += __shfl_xor_sync(0xffffffffu, v, off);
    return v;
}
__device__ __forceinline__ float warp_max(float v) {
#pragma unroll
    for (int off = 16; off; off >>= 1) v = fmaxf(v, __shfl_xor_sync(0xffffffffu, v, off));
    return v;
}

// ---------------- initial pass: all 127 pairs, loss + y cache ----------------
// grid (127, 8), 256 threads: 2 batch rows per block. Per-output q-loop order
// identical to prior rounds -> bit-identical g_y / g_loss.
__global__ void k_init_pairs() {
    int j  = blockIdx.x;
    int rg = blockIdx.y;                 // rows rg*2 .. rg*2+1
    __shared__ __align__(16) float sIn[2][256];
    __shared__ __align__(16) float sY[2][128];
    __shared__ __align__(16) float sXX[2][256];
    __shared__ float sLS[2][2];
    int t = threadIdx.x, lane = t & 31, wid = t >> 5;

    for (int i = t; i < 512; i += 256) {
        int r = i >> 8, k = i & 255;
        int b = rg * 2 + r;
        sIn[r][k] = (k < 128) ? g_nodes[b][j + 1][k] : g_nodes[b][j][k - 128];
    }
    __syncthreads();

    // layer1: 2 rows x 128 outs, 1/thread
    {
        int r = t >> 7, o = t & 127;
        int b = rg * 2 + r;
        const float4* W = (const float4*)g_W12B;
        const float4* X = (const float4*)sIn[r];
        float acc = 0.f;
#pragma unroll 8
        for (int q = 0; q < 64; q++) {
            float4 w = W[q * 128 + o]; float4 x = X[q];
            acc += w.x * x.x + w.y * x.y + w.z * x.z + w.w * x.w;
        }
        acc += g_b12[o];
        sY[r][o] = acc;
        g_y[b][j][o] = acc;
    }
    __syncthreads();

    // layer2: 2 rows x 256 outs, 2/thread
    for (int ii = 0; ii < 2; ii++) {
        int oi = t + ii * 256;
        int r = oi >> 8, o = oi & 255;
        const float4* W = (const float4*)g_W34B;
        const float4* X = (const float4*)sY[r];
        float acc = 0.f;
#pragma unroll 8
        for (int q = 0; q < 32; q++) {
            float4 w = W[q * 256 + o]; float4 x = X[q];
            acc += w.x * x.x + w.y * x.y + w.z * x.z + w.w * x.w;
        }
        sXX[r][o] = acc + g_b34[o];
    }
    __syncthreads();

    // ls per (row, half): 4 warps (identical per-warp sequence as before)
    if (wid < 4) {
        int r = wid >> 1, h = wid & 1;
        const float* x  = sXX[r] + h * 128;
        const float* nd = sIn[r] + h * 128;
        float mx = -CUDART_INF_F;
        for (int i2 = lane; i2 < 128; i2 += 32) mx = fmaxf(mx, x[i2]);
        mx = warp_max(mx);
        float se = 0.f, dt = 0.f, sn = 0.f;
        for (int i2 = lane; i2 < 128; i2 += 32) {
            float xv = x[i2], nv = nd[i2];
            se += expf(xv - mx); dt += nv * xv; sn += nv;
        }
        se = warp_sum(se); dt = warp_sum(dt); sn = warp_sum(sn);
        if (lane == 0) sLS[r][h] = sn * (mx + logf(se)) - dt;
    }
    __syncthreads();
    if (t < 2) {
        int b = rg * 2 + t;
        g_loss[b][j] = ((1.f + EPSF) * sLS[t][0] + (1.f + EPSF) * sLS[t][1]) / (2.f + EPSF);
    }
}

// ---------------- persistent scan: one CTA per batch (R15 verbatim) ----------------
// dyn smem: sW34h (65536B, q rows {8..15,24..31}) + nodeSm (65536B) + ySm (65024B)
#define DYN_BYTES (65536 + 65536 + 65024)

__global__ void __launch_bounds__(512, 1)
k_scan(const float* __restrict__ Wk, const float* __restrict__ bk, float* __restrict__ out) {
    extern __shared__ __align__(16) float dyn[];
    float* sW34h  = dyn;               // 16384 floats: q in {8..15,24..31}
    float* nodeSm = dyn + 16384;       // 128*128 floats: leaf nodes
    float* ySm    = dyn + 32768;       // 127*128 floats, row = slot
    int b = blockIdx.x;
    int t = threadIdx.x, lane = t & 31, wid = t >> 5;

    // double-buffered scan state (parity-indexed)
    __shared__ int   permB[2][SS];     // <128: leaf row (nodeSm), >=128: ySm slot+128
    __shared__ float countsB[2][SS];
    __shared__ __align__(16) float lossB[2][SS];
    __shared__ int   ypermB[2][SS];
    __shared__ __align__(16) float sIn[2][256];     // linear (softmax)
    __shared__ __align__(16) float sInSw[2][256];   // k-swizzled: unit p=4i+h1
    __shared__ __align__(16) float sYSw[2][128];    // k-swizzled: unit p=2i+h2
    __shared__ __align__(16) float sXX[2][256];
    __shared__ float b12s[128], b34s[256];
    __shared__ float sAcc;
    __shared__ float logits[8];

    const float INFV = CUDART_INF_F;

    // thread mappings
    int o1 = (t & 7) | ((t >> 2) & 0x78);     // layer1 output 0..127
    int h1 = (t >> 3) & 3;                    // layer1 k-split
    int o2 = (t & 15) | ((t >> 1) & 0xF0);    // layer2 output 0..255
    int h2 = (t >> 4) & 1;                    // layer2 k-split

    // one-time staging
    for (int i = t; i < 4096; i += 512) {     // W34 smem half
        int r = i >> 8;
        int q = (r < 8) ? (r + 8) : (r + 16);
        ((float4*)sW34h)[i] = ((const float4*)g_W34B)[q * 256 + (i & 255)];
    }
    for (int i = t; i < 4096; i += 512)       // leaves
        ((float4*)nodeSm)[i] = ((const float4*)g_nodes[b])[i];
    for (int i = t; i < 4064; i += 512)       // y cache
        ((float4*)ySm)[i] = ((const float4*)g_y[b])[i];
    if (t < 128) b12s[t] = g_b12[t];
    if (t < 256) b34s[t] = g_b34[t];
    if (t < SS) {
        permB[0][t] = t; countsB[0][t] = 1.f; ypermB[0][t] = t;
        lossB[0][t] = (t < NP) ? g_loss[b][t] : INFV;
    }
    if (t == 0) sAcc = 0.f;

    // W12 slice into registers (64 regs)
    ulonglong2 wr12[16];
#pragma unroll
    for (int i = 0; i < 16; i++)
        wr12[i] = ((const ulonglong2*)g_W12B)[(h1 * 16 + i) * 128 + o1];
    // W34 first-half slice into registers (32 regs)
    ulonglong2 wr34h[8];
#pragma unroll
    for (int i = 0; i < 8; i++)
        wr34h[i] = ((const ulonglong2*)g_W34B)[(h2 * 16 + i) * 256 + o2];
    __syncthreads();

    int L = SS;
    int par = 0;
    for (int step = 0; step < SS - 1; step++) {
        int*   permC = permB[par];   float* cntC  = countsB[par];
        float* lossC = lossB[par];   int*   ypC   = ypermB[par];
        int np = par ^ 1;
        int*   permN = permB[np];    float* cntN  = countsB[np];
        float* lossN = lossB[np];    int*   ypN   = ypermB[np];

        // ---- P1: argmin, redundant in EVERY warp (no barrier) ----
        float4 lv4 = ((const float4*)lossC)[lane];
        int base = lane * 4;
        float v = (base < L - 1) ? lv4.x : INFV;
        int vi = base;
        if (base + 1 < L - 1 && lv4.y < v) { v = lv4.y; vi = base + 1; }
        if (base + 2 < L - 1 && lv4.z < v) { v = lv4.z; vi = base + 2; }
        if (base + 3 < L - 1 && lv4.w < v) { v = lv4.w; vi = base + 3; }
        unsigned key = fkey(v);
        unsigned kmin = __reduce_min_sync(0xffffffffu, key);
        unsigned msk = __ballot_sync(0xffffffffu, key == kmin);
        int srcl = __ffs(msk) - 1;
        int idx = __shfl_sync(0xffffffffu, vi, srcl);
        float vw = __shfl_sync(0xffffffffu, v, srcl);
        if (t == 0) sAcc += vw;

        // ---- P2: scalar derivation + reads from OLD buffer ----
        int Ln = L - 1;
        int pos = (idx > 0) ? idx - 1 : 0;
        int lc  = (idx == 0) ? (L - 1) : (idx - 1);
        float fcnt = cntC[idx] + cntC[lc];
        int yF = ypC[idx];
        bool hasA = (idx > 0) && (pos >= 1);
        bool hasB = (pos <= Ln - 2);
        int rOld = (idx == 0) ? 1 : (pos + 2);
        int slotA = hasA ? ypC[pos - 1] : 0;
        int slotB = ypC[pos];
        float cA2 = hasA ? cntC[pos - 1] : 0.f;
        float cB1 = hasB ? cntC[rOld] : 0.f;
        int srcA = hasA ? permC[pos - 1] : 0;
        int srcB = hasB ? permC[rOld] : 0;
        const float* pA = (srcA < 128) ? (nodeSm + srcA * 128) : (ySm + (srcA - 128) * 128);
        const float* pB = (srcB < 128) ? (nodeSm + srcB * 128) : (ySm + (srcB - 128) * 128);

        // unified copy source (stale tails land in never-read slots)
        int pv = 0, yv = 0; float cv = 0.f, lv = 0.f;
        float4 gv = make_float4(0.f, 0.f, 0.f, 0.f);
        if (t < 128) {
            int srcI = (idx > 0 && t > pos && t < 127) ? t + 1 : t;
            pv = permC[srcI]; cv = cntC[srcI];
            lv = lossC[srcI]; yv = ypC[srcI];
            int p = t >> 6, q4 = t & 63;
            if (p == 0) {
                if (q4 < 32) gv = ((const float4*)(ySm + yF * 128))[q4];
                else if (hasA) gv = ((const float4*)pA)[q4 - 32];
            } else {
                if (q4 >= 32) gv = ((const float4*)(ySm + yF * 128))[q4 - 32];
                else if (hasB) gv = ((const float4*)pB)[q4];
            }
        }

        // ---- P3: writes to NEW buffer + sIn (disjoint from OLD: no barrier) ----
        if (t < 128) {
            permN[t] = (t == pos) ? (128 + yF) : pv;
            cntN[t]  = (t == pos) ? fcnt : cv;
            lossN[t] = lv; ypN[t] = yv;
            int p = t >> 6, q4 = t & 63;
            ((float4*)sIn[p])[q4] = gv;
            int sw = ((q4 & 15) << 2) | (q4 >> 4);
            ((float4*)sInSw[p])[sw] = gv;
        }
        __syncthreads();   // B1

        // ---- P4: layer1 (W12 regs, conflict-free swizzled x) ----
        {
            const ulonglong2* XA = (const ulonglong2*)sInSw[0];
            const ulonglong2* XB = (const ulonglong2*)sInSw[1];
            unsigned long long a0 = 0, a1 = 0, c0 = 0, c1 = 0;
#pragma unroll
            for (int i = 0; i < 16; i++) {
                ulonglong2 w = wr12[i];
                ulonglong2 xa = XA[i * 4 + h1], xb = XB[i * 4 + h1];
                fma2(a0, w.x, xa.x); fma2(a1, w.y, xa.y);
                fma2(c0, w.x, xb.x); fma2(c1, w.y, xb.y);
            }
            float yA = sum2(a0) + sum2(a1);
            float yB = sum2(c0) + sum2(c1);
            yA += __shfl_xor_sync(0xffffffffu, yA, 8);
            yA += __shfl_xor_sync(0xffffffffu, yA, 16);
            yB += __shfl_xor_sync(0xffffffffu, yB, 8);
            yB += __shfl_xor_sync(0xffffffffu, yB, 16);
            if (h1 == 0) {
                yA += b12s[o1]; yB += b12s[o1];
                int q = o1 >> 2;
                int idxSw = ((((q & 15) << 1) | (q >> 4)) << 2) | (o1 & 3);
                sYSw[0][idxSw] = yA; sYSw[1][idxSw] = yB;
                if (hasA) ySm[slotA * 128 + o1] = yA;
                if (hasB) ySm[slotB * 128 + o1] = yB;
            }
        }
        __syncthreads();   // B2

        // ---- P5: layer2 (W34 half regs + half smem) ----
        {
            const ulonglong2* Wv = (const ulonglong2*)sW34h;
            const ulonglong2* YA = (const ulonglong2*)sYSw[0];
            const ulonglong2* YB = (const ulonglong2*)sYSw[1];
            unsigned long long a0 = 0, a1 = 0, c0 = 0, c1 = 0;
#pragma unroll
            for (int i = 0; i < 8; i++) {
                ulonglong2 w = wr34h[i];
                ulonglong2 ya = YA[i * 2 + h2], yb = YB[i * 2 + h2];
                fma2(a0, w.x, ya.x); fma2(a1, w.y, ya.y);
                fma2(c0, w.x, yb.x); fma2(c1, w.y, yb.y);
            }
#pragma unroll
            for (int i = 8; i < 16; i++) {
                ulonglong2 w = Wv[((i - 8) + h2 * 8) * 256 + o2];
                ulonglong2 ya = YA[i * 2 + h2], yb = YB[i * 2 + h2];
                fma2(a0, w.x, ya.x); fma2(a1, w.y, ya.y);
                fma2(c0, w.x, yb.x); fma2(c1, w.y, yb.y);
            }
            float xA = sum2(a0) + sum2(a1);
            float xB = sum2(c0) + sum2(c1);
            xA += __shfl_xor_sync(0xffffffffu, xA, 16);
            xB += __shfl_xor_sync(0xffffffffu, xB, 16);
            if (h2 == 0) {
                sXX[0][o2] = xA + b34s[o2];
                sXX[1][o2] = xB + b34s[o2];
            }
        }
        __syncthreads();   // B3

        // ---- P6: softmax + loss write, ONE warp per pair (warps 0-1) ----
        if (wid < 2) {
            int p = wid;                 // pair
            int h = lane >> 4;           // half (0: ls1/right, 1: ls2/left)
            int l16 = lane & 15;
            const float* x  = sXX[p] + h * 128 + l16 * 8;
            const float* nd = sIn[p] + h * 128 + l16 * 8;
            float4 x0 = ((const float4*)x)[0], x1 = ((const float4*)x)[1];
            float4 n0 = ((const float4*)nd)[0], n1 = ((const float4*)nd)[1];
            float mx = fmaxf(fmaxf(fmaxf(x0.x, x0.y), fmaxf(x0.z, x0.w)),
                             fmaxf(fmaxf(x1.x, x1.y), fmaxf(x1.z, x1.w)));
#pragma unroll
            for (int s = 1; s <= 8; s <<= 1) mx = fmaxf(mx, __shfl_xor_sync(0xffffffffu, mx, s));
            float se = (expf(x0.x - mx) + expf(x0.y - mx)) + (expf(x0.z - mx) + expf(x0.w - mx))
                     + (expf(x1.x - mx) + expf(x1.y - mx)) + (expf(x1.z - mx) + expf(x1.w - mx));
            float dt = (n0.x * x0.x + n0.y * x0.y) + (n0.z * x0.z + n0.w * x0.w)
                     + (n1.x * x1.x + n1.y * x1.y) + (n1.z * x1.z + n1.w * x1.w);
            float sn = (n0.x + n0.y) + (n0.z + n0.w) + (n1.x + n1.y) + (n1.z + n1.w);
#pragma unroll
            for (int s = 1; s <= 8; s <<= 1) {
                se += __shfl_xor_sync(0xffffffffu, se, s);
                dt += __shfl_xor_sync(0xffffffffu, dt, s);
                sn += __shfl_xor_sync(0xffffffffu, sn, s);
            }
            float ls = sn * (mx + logf(se)) - dt;
            float lsOther = __shfl_xor_sync(0xffffffffu, ls, 16);
            if (lane == 0) {
                float ls1 = ls, ls2 = lsOther;
                if (p == 0) {
                    if (hasA) lossN[pos - 1] = ((fcnt + EPSF) * ls1 + (cA2 + EPSF) * ls2) / (fcnt + cA2 + EPSF);
                } else {
                    if (hasB) lossN[pos] = ((cB1 + EPSF) * ls1 + (fcnt + EPSF) * ls2) / (cB1 + fcnt + EPSF);
                }
            }
        }
        __syncthreads();   // B4 (loss writes visible for next P1)

        L = Ln;
        par = np;
    }

    // ---- final classifier on root node ----
    if (t < 5) {
        int src = permB[par][0];
        const float* root = (src < 128) ? (nodeSm + src * 128) : (ySm + (src - 128) * 128);
        float a = bk[t];
#pragma unroll 8
        for (int k2 = 0; k2 < 128; k2++) a += root[k2] * Wk[k2 * 5 + t];
        logits[t] = a;
    }
    __syncthreads();
    if (t == 0) {
        int best = 0; float bv = logits[0];
#pragma unroll
        for (int o = 1; o < 5; o++) if (logits[o] > bv) { bv = logits[o]; best = o; }
        out[b] = (float)best;
        g_accv[b] = sAcc;
    }
}

// ---------------- finalize: mean acc ----------------
__global__ void k_final(float* out) {
    int t = threadIdx.x;
    float v = (t < BB) ? g_accv[t] : 0.f;
#pragma unroll
    for (int off = 16; off; off >>= 1) v += __shfl_down_sync(0xffffffffu, v, off);
    if (t == 0) out[BB] = v / (float)BB;
}

// ---------------- launcher ----------------
extern "C" void kernel_launch(void* const* d_in, const int* in_sizes, int n_in,
                              void* d_out, int out_size) {
    const void*  inp = d_in[0];
    const float* emb = (const float*)d_in[1];
    const float* W1 = (const float*)d_in[2];
    const float* b1 = (const float*)d_in[3];
    const float* W2 = (const float*)d_in[4];
    const float* b2 = (const float*)d_in[5];
    const float* W3 = (const float*)d_in[6];
    const float* b3 = (const float*)d_in[7];
    const float* W4 = (const float*)d_in[8];
    const float* b4 = (const float*)d_in[9];
    const float* Wk = (const float*)d_in[10];
    const float* bk = (const float*)d_in[11];
    float* out = (float*)d_out;

    static bool attr_set = false;
    if (!attr_set) {
        cudaFuncSetAttribute(k_scan, cudaFuncAttributeMaxDynamicSharedMemorySize, DYN_BYTES);
        attr_set = true;
    }

    kfuse<<<386, 256>>>(W1, b1, W2, b2, W3, b3, W4, b4);
    k_embed<<<(BB * SS * MM + 511) / 512, 512>>>(inp, emb);
    k_init_pairs<<<dim3(NP, 8), 256>>>();
    k_scan<<<BB, 512, DYN_BYTES>>>(Wk, bk, out);
    k_final<<<1, 32>>>(out);
}